// round 3
// baseline (speedup 1.0000x reference)
#include <cuda_runtime.h>
#include <cstdint>

#define NSEG   10000
#define D      128
#define BM     64
#define BLK_B  256
#define TBLK   16                     // transpose blocks prepended to sum grid
#define SEGS_PER_BLK 8
#define XS_STRIDE 132                 // pad x rows (132*4B, 16B-aligned)
#define SMEM_B ((D * D + BM * XS_STRIDE) * 4)   // 99328 bytes

// Scratch (no allocations allowed): per-segment sums + transposed W.
__device__ float g_sums[NSEG * D];
__device__ float g_WT[D * D];     // g_WT[k*D + n] = W[n*D + k]

// graph may be int32 or int64 depending on jax x64 config.
// int32 layout: word[2*NSEG-1] = ends[NSEG-1] = N-1 (nonzero).
// int64 layout: word[2*NSEG-1] = high half of element NSEG-1 -> 0.
__device__ __forceinline__ void load_seg(const int* __restrict__ g, int s,
                                         int& st, int& en) {
    bool is64 = (g[2 * NSEG - 1] == 0);
    if (is64) {
        const long long* g64 = (const long long*)g;
        st = (int)g64[2 * s];
        en = (int)g64[2 * s + 1];
    } else {
        st = g[2 * s];
        en = g[2 * s + 1];
    }
}

// ---------------------------------------------------------------------------
// Kernel 1: blocks [0,TBLK) transpose W into g_WT (hidden under the
// memory-bound sum phase). Blocks [TBLK, ...) do segment sums:
// one WARP per segment, lane = float4 column, unroll-4 rows
// (4 independent LDG.128 in flight), no smem, no syncs.
// ---------------------------------------------------------------------------
__global__ void __launch_bounds__(256) sum_kernel(
    const float* __restrict__ input,
    const int*   __restrict__ graph,
    const float* __restrict__ W)
{
    if (blockIdx.x < TBLK) {
        // Transpose: coalesced writes, scattered reads (64KB, L2-resident).
        int base = blockIdx.x * (D * D / TBLK);          // 1024 elems per block
#pragma unroll
        for (int i = 0; i < (D * D / TBLK) / 256; i++) { // 4 iters
            int lin = base + threadIdx.x + i * 256;
            int k = lin >> 7;
            int n = lin & 127;
            g_WT[lin] = W[n * D + k];
        }
        return;
    }

    const int warp = threadIdx.x >> 5;
    const int lane = threadIdx.x & 31;
    const int seg  = (blockIdx.x - TBLK) * SEGS_PER_BLK + warp;
    if (seg >= NSEG) return;

    int start, end;
    load_seg(graph, seg, start, end);
    const int n = end - start + 1;

    const float4* p = (const float4*)input + (long long)start * 32 + lane;

    float4 acc = make_float4(0.f, 0.f, 0.f, 0.f);
    int r = 0;
    for (; r + 4 <= n; r += 4) {
        float4 v0 = p[0];
        float4 v1 = p[32];
        float4 v2 = p[64];
        float4 v3 = p[96];
        acc.x += (v0.x + v1.x) + (v2.x + v3.x);
        acc.y += (v0.y + v1.y) + (v2.y + v3.y);
        acc.z += (v0.z + v1.z) + (v2.z + v3.z);
        acc.w += (v0.w + v1.w) + (v2.w + v3.w);
        p += 128;
    }
    for (; r < n; ++r) {
        float4 v = p[0];
        acc.x += v.x; acc.y += v.y; acc.z += v.z; acc.w += v.w;
        p += 32;
    }
    ((float4*)g_sums)[seg * 32 + lane] = acc;
}

// ---------------------------------------------------------------------------
// Kernel 2: out[m][n] = sum_k xs[m][k] * WT[k][n] + cnt_m * b[n]
// Register-blocked GEMM with PACKED f32x2 FMA (2 lane-FMA per issue).
// BM=64 segments/block, 256 threads, thread = 4 m x 8 n (= 4 m x 4 pairs).
// ---------------------------------------------------------------------------
__global__ void __launch_bounds__(BLK_B) seg_gemm_kernel(
    const int*   __restrict__ graph,
    const float* __restrict__ b,
    float*       __restrict__ out)
{
    extern __shared__ float sm[];
    float* ws = sm;            // ws[k*D + n]  (64KB, layout-identical copy)
    float* xs = sm + D * D;    // xs[m*XS_STRIDE + k]

    const int tid = threadIdx.x;
    const int m0  = blockIdx.x * BM;

    // Stage W^T: straight float4 copy, coalesced, conflict-free.
    {
        const float4* src = (const float4*)g_WT;
#pragma unroll
        for (int i = 0; i < (D * D / 4) / BLK_B; i++) {    // 16 iters
            int lin = tid + i * BLK_B;
            ((float4*)ws)[lin] = src[lin];
        }
    }
    // Stage x tile.
    {
#pragma unroll
        for (int i = 0; i < (BM * D / 4) / BLK_B; i++) {   // 8 iters
            int lin = tid + i * BLK_B;
            int m   = lin >> 5;
            int k4  = lin & 31;
            int seg = m0 + m;
            float4 v = make_float4(0.f, 0.f, 0.f, 0.f);
            if (seg < NSEG) v = ((const float4*)g_sums)[seg * 32 + k4];
            *(float4*)(xs + m * XS_STRIDE + k4 * 4) = v;
        }
    }
    __syncthreads();

    const int tx = tid & 15;    // n-group: n = tx*8 .. tx*8+7 (4 f32 pairs)
    const int ty = tid >> 4;    // m-group: m = ty*4 .. ty*4+3

    // Accumulators: 4 m x 4 packed-f32x2 (covering 8 n).
    unsigned long long acc2[4][4];
#pragma unroll
    for (int i = 0; i < 4; i++)
#pragma unroll
        for (int j = 0; j < 4; j++) acc2[i][j] = 0ull;

    const float* xp0 = xs + (ty * 4 + 0) * XS_STRIDE;
    const float* xp1 = xs + (ty * 4 + 1) * XS_STRIDE;
    const float* xp2 = xs + (ty * 4 + 2) * XS_STRIDE;
    const float* xp3 = xs + (ty * 4 + 3) * XS_STRIDE;
    // W row k for this thread's 8 n's, viewed as 4 b64 pairs.
    const unsigned long long* wp =
        (const unsigned long long*)(ws) + tx * 4;   // (floats tx*8..tx*8+7)

#pragma unroll 8
    for (int k = 0; k < D; k++) {
        const unsigned long long* wk = wp + k * (D / 2);
        unsigned long long w0 = wk[0];
        unsigned long long w1 = wk[1];
        unsigned long long w2 = wk[2];
        unsigned long long w3 = wk[3];

        float x0 = xp0[k], x1 = xp1[k], x2 = xp2[k], x3 = xp3[k];
        unsigned long long xx0, xx1, xx2, xx3;
        asm("mov.b64 %0, {%1, %1};" : "=l"(xx0) : "f"(x0));
        asm("mov.b64 %0, {%1, %1};" : "=l"(xx1) : "f"(x1));
        asm("mov.b64 %0, {%1, %1};" : "=l"(xx2) : "f"(x2));
        asm("mov.b64 %0, {%1, %1};" : "=l"(xx3) : "f"(x3));

#define FMA2(i, xx, w, j) \
        asm("fma.rn.f32x2 %0, %1, %2, %0;" : "+l"(acc2[i][j]) : "l"(xx), "l"(w))
        FMA2(0, xx0, w0, 0); FMA2(0, xx0, w1, 1);
        FMA2(0, xx0, w2, 2); FMA2(0, xx0, w3, 3);
        FMA2(1, xx1, w0, 0); FMA2(1, xx1, w1, 1);
        FMA2(1, xx1, w2, 2); FMA2(1, xx1, w3, 3);
        FMA2(2, xx2, w0, 0); FMA2(2, xx2, w1, 1);
        FMA2(2, xx2, w2, 2); FMA2(2, xx2, w3, 3);
        FMA2(3, xx3, w0, 0); FMA2(3, xx3, w1, 1);
        FMA2(3, xx3, w2, 2); FMA2(3, xx3, w3, 3);
#undef FMA2
    }

    // Epilogue: + count * b, vectorized stores.
    float4 b0 = ((const float4*)b)[tx * 2];
    float4 b1 = ((const float4*)b)[tx * 2 + 1];

#pragma unroll
    for (int i = 0; i < 4; i++) {
        int seg = m0 + ty * 4 + i;
        if (seg >= NSEG) continue;
        int st, en;
        load_seg(graph, seg, st, en);
        float cnt = (float)(en - st + 1);

        float a0, a1, a2, a3, a4, a5, a6, a7;
        asm("mov.b64 {%0, %1}, %2;" : "=f"(a0), "=f"(a1) : "l"(acc2[i][0]));
        asm("mov.b64 {%0, %1}, %2;" : "=f"(a2), "=f"(a3) : "l"(acc2[i][1]));
        asm("mov.b64 {%0, %1}, %2;" : "=f"(a4), "=f"(a5) : "l"(acc2[i][2]));
        asm("mov.b64 {%0, %1}, %2;" : "=f"(a6), "=f"(a7) : "l"(acc2[i][3]));

        float4 o0, o1;
        o0.x = a0 + cnt * b0.x;
        o0.y = a1 + cnt * b0.y;
        o0.z = a2 + cnt * b0.z;
        o0.w = a3 + cnt * b0.w;
        o1.x = a4 + cnt * b1.x;
        o1.y = a5 + cnt * b1.y;
        o1.z = a6 + cnt * b1.z;
        o1.w = a7 + cnt * b1.w;

        float4* op = (float4*)(out + (long long)seg * D + tx * 8);
        op[0] = o0;
        op[1] = o1;
    }
}

extern "C" void kernel_launch(void* const* d_in, const int* in_sizes, int n_in,
                              void* d_out, int out_size) {
    const float* input = (const float*)d_in[0];
    const int*   graph = (const int*)  d_in[1];
    const float* W     = (const float*)d_in[2];
    const float* b     = (const float*)d_in[3];
    float*       out   = (float*)d_out;

    cudaFuncSetAttribute(seg_gemm_kernel,
                         cudaFuncAttributeMaxDynamicSharedMemorySize, SMEM_B);

    int sum_grid = TBLK + (NSEG + SEGS_PER_BLK - 1) / SEGS_PER_BLK;
    sum_kernel<<<sum_grid, 256>>>(input, graph, W);
    seg_gemm_kernel<<<(NSEG + BM - 1) / BM, BLK_B, SMEM_B>>>(graph, b, out);
}

// round 4
// speedup vs baseline: 1.6249x; 1.6249x over previous
#include <cuda_runtime.h>
#include <cstdint>

#define NSEG   10000
#define D      128
#define BM     72
#define BLK_B  288
#define TBLK   16
#define XS_STRIDE 132
#define SMEM_B ((D * D + BM * XS_STRIDE) * 4)   // 103552 bytes

__device__ float g_sums[NSEG * D];
__device__ float g_WT[D * D];     // g_WT[k*D + n] = W[n*D + k]

// graph may be int32 or int64 depending on jax x64 config.
// int32 layout: word[2*NSEG-1] = ends[NSEG-1] = N-1 (nonzero).
// int64 layout: word[2*NSEG-1] = high half of element NSEG-1 -> 0.
__device__ __forceinline__ void load_seg(const int* __restrict__ g, int s,
                                         int& st, int& en) {
    bool is64 = (g[2 * NSEG - 1] == 0);
    if (is64) {
        const long long* g64 = (const long long*)g;
        st = (int)g64[2 * s];
        en = (int)g64[2 * s + 1];
    } else {
        st = g[2 * s];
        en = g[2 * s + 1];
    }
}

// ---------------------------------------------------------------------------
// Kernel 1: blocks [0,TBLK) transpose W into g_WT (hidden under the memory
// phase). Blocks [TBLK,...): one block per segment, 128 threads. Warp w
// handles rows start+w+16i+{0,4,8,12}: 4 independent LDG.128 in flight per
// warp, 16 per block. Cross-warp reduce via smem.
// ---------------------------------------------------------------------------
__global__ void __launch_bounds__(128) sum_kernel(
    const float* __restrict__ input,
    const int*   __restrict__ graph,
    const float* __restrict__ W)
{
    if (blockIdx.x < TBLK) {
        int base = blockIdx.x * (D * D / TBLK);          // 1024 elems/block
#pragma unroll
        for (int i = 0; i < (D * D / TBLK) / 128; i++) { // 8 iters
            int lin = base + threadIdx.x + i * 128;
            int k = lin >> 7;
            int n = lin & 127;
            g_WT[lin] = W[n * D + k];
        }
        return;
    }

    const int s    = blockIdx.x - TBLK;
    const int c4   = threadIdx.x & 31;   // float4 column within row
    const int rl   = threadIdx.x >> 5;   // warp id 0..3

    int start, end;
    load_seg(graph, s, start, end);
    const int n = end - start + 1;

    const float4* base = (const float4*)input + (long long)start * 32 + c4;

    float4 acc = make_float4(0.f, 0.f, 0.f, 0.f);
    int r = rl;
    // Warp handles rows rl+16i+{0,4,8,12}: 4 independent LDG.128 in flight.
    for (; r + 12 < n; r += 16) {
        const float4* p = base + (long long)r * 32;
        float4 v0 = p[0 * 32];
        float4 v1 = p[4 * 32];
        float4 v2 = p[8 * 32];
        float4 v3 = p[12 * 32];
        acc.x += (v0.x + v1.x) + (v2.x + v3.x);
        acc.y += (v0.y + v1.y) + (v2.y + v3.y);
        acc.z += (v0.z + v1.z) + (v2.z + v3.z);
        acc.w += (v0.w + v1.w) + (v2.w + v3.w);
    }
    for (; r < n; r += 4) {
        float4 v = base[(long long)r * 32];
        acc.x += v.x; acc.y += v.y; acc.z += v.z; acc.w += v.w;
    }

    __shared__ float4 red[4][32];
    red[rl][c4] = acc;
    __syncthreads();
    if (rl == 0) {
        float4 a = red[0][c4], b2 = red[1][c4], c = red[2][c4], d = red[3][c4];
        float4 t;
        t.x = (a.x + b2.x) + (c.x + d.x);
        t.y = (a.y + b2.y) + (c.y + d.y);
        t.z = (a.z + b2.z) + (c.z + d.z);
        t.w = (a.w + b2.w) + (c.w + d.w);
        ((float4*)g_sums)[s * 32 + c4] = t;
    }
}

// ---------------------------------------------------------------------------
// Kernel 2: out[m][n] = sum_k xs[m][k] * WT[k][n] + cnt_m * b[n]
// BM=72 segments/block, 288 threads -> 139 blocks = ONE wave on 148 SMs.
// Thread (ty,tx): 4 m x 8 n register tile, plain FFMA.
// ---------------------------------------------------------------------------
__global__ void __launch_bounds__(BLK_B) seg_gemm_kernel(
    const int*   __restrict__ graph,
    const float* __restrict__ b,
    float*       __restrict__ out)
{
    extern __shared__ float sm[];
    float* ws = sm;            // ws[k*D + n]  (64KB copy of g_WT)
    float* xs = sm + D * D;    // xs[m*XS_STRIDE + k]

    const int tid = threadIdx.x;
    const int m0  = blockIdx.x * BM;

    // Stage W^T: straight float4 copy, coalesced.
    {
        const float4* src = (const float4*)g_WT;
        for (int lin = tid; lin < D * D / 4; lin += BLK_B)
            ((float4*)ws)[lin] = src[lin];
    }
    // Stage x tile (72 rows x 32 float4 = 2304 = 8 * 288).
    {
#pragma unroll
        for (int i = 0; i < (BM * D / 4) / BLK_B; i++) {   // 8 iters
            int lin = tid + i * BLK_B;
            int m   = lin >> 5;
            int k4  = lin & 31;
            int seg = m0 + m;
            float4 v = make_float4(0.f, 0.f, 0.f, 0.f);
            if (seg < NSEG) v = ((const float4*)g_sums)[seg * 32 + k4];
            *(float4*)(xs + m * XS_STRIDE + k4 * 4) = v;
        }
    }
    __syncthreads();

    const int tx = tid & 15;    // n-group: n = tx*8 .. tx*8+7
    const int ty = tid >> 4;    // m-group: m = ty*4 .. ty*4+3  (0..17)

    float acc[4][8];
#pragma unroll
    for (int i = 0; i < 4; i++)
#pragma unroll
        for (int j = 0; j < 8; j++) acc[i][j] = 0.f;

    const float* xp0 = xs + (ty * 4 + 0) * XS_STRIDE;
    const float* xp1 = xs + (ty * 4 + 1) * XS_STRIDE;
    const float* xp2 = xs + (ty * 4 + 2) * XS_STRIDE;
    const float* xp3 = xs + (ty * 4 + 3) * XS_STRIDE;
    const float* wp  = ws + tx * 8;

#pragma unroll 8
    for (int k = 0; k < D; k++) {
        float4 w0 = *(const float4*)(wp + k * D);
        float4 w1 = *(const float4*)(wp + k * D + 4);
        float x0 = xp0[k], x1 = xp1[k], x2 = xp2[k], x3 = xp3[k];

        acc[0][0] += x0 * w0.x; acc[0][1] += x0 * w0.y;
        acc[0][2] += x0 * w0.z; acc[0][3] += x0 * w0.w;
        acc[0][4] += x0 * w1.x; acc[0][5] += x0 * w1.y;
        acc[0][6] += x0 * w1.z; acc[0][7] += x0 * w1.w;

        acc[1][0] += x1 * w0.x; acc[1][1] += x1 * w0.y;
        acc[1][2] += x1 * w0.z; acc[1][3] += x1 * w0.w;
        acc[1][4] += x1 * w1.x; acc[1][5] += x1 * w1.y;
        acc[1][6] += x1 * w1.z; acc[1][7] += x1 * w1.w;

        acc[2][0] += x2 * w0.x; acc[2][1] += x2 * w0.y;
        acc[2][2] += x2 * w0.z; acc[2][3] += x2 * w0.w;
        acc[2][4] += x2 * w1.x; acc[2][5] += x2 * w1.y;
        acc[2][6] += x2 * w1.z; acc[2][7] += x2 * w1.w;

        acc[3][0] += x3 * w0.x; acc[3][1] += x3 * w0.y;
        acc[3][2] += x3 * w0.z; acc[3][3] += x3 * w0.w;
        acc[3][4] += x3 * w1.x; acc[3][5] += x3 * w1.y;
        acc[3][6] += x3 * w1.z; acc[3][7] += x3 * w1.w;
    }

    float4 b0 = ((const float4*)b)[tx * 2];
    float4 b1 = ((const float4*)b)[tx * 2 + 1];

#pragma unroll
    for (int i = 0; i < 4; i++) {
        int seg = m0 + ty * 4 + i;
        if (seg >= NSEG) continue;
        int st, en;
        load_seg(graph, seg, st, en);
        float cnt = (float)(en - st + 1);

        float4 o0, o1;
        o0.x = acc[i][0] + cnt * b0.x;
        o0.y = acc[i][1] + cnt * b0.y;
        o0.z = acc[i][2] + cnt * b0.z;
        o0.w = acc[i][3] + cnt * b0.w;
        o1.x = acc[i][4] + cnt * b1.x;
        o1.y = acc[i][5] + cnt * b1.y;
        o1.z = acc[i][6] + cnt * b1.z;
        o1.w = acc[i][7] + cnt * b1.w;

        float4* op = (float4*)(out + (long long)seg * D + tx * 8);
        op[0] = o0;
        op[1] = o1;
    }
}

extern "C" void kernel_launch(void* const* d_in, const int* in_sizes, int n_in,
                              void* d_out, int out_size) {
    const float* input = (const float*)d_in[0];
    const int*   graph = (const int*)  d_in[1];
    const float* W     = (const float*)d_in[2];
    const float* b     = (const float*)d_in[3];
    float*       out   = (float*)d_out;

    cudaFuncSetAttribute(seg_gemm_kernel,
                         cudaFuncAttributeMaxDynamicSharedMemorySize, SMEM_B);

    sum_kernel<<<TBLK + NSEG, 128>>>(input, graph, W);
    seg_gemm_kernel<<<(NSEG + BM - 1) / BM, BLK_B, SMEM_B>>>(graph, b, out);
}

// round 5
// speedup vs baseline: 1.6812x; 1.0346x over previous
#include <cuda_runtime.h>
#include <cstdint>

#define NSEG   10000
#define D      128
#define BM     72
#define BLK_B  288
#define TBLK   16
#define XS_STRIDE 132
#define SMEM_B ((D * D + BM * XS_STRIDE) * 4)   // 103552 bytes

__device__ float g_sums[NSEG * D];
__device__ float g_WT[D * D];     // g_WT[k*D + n] = W[n*D + k]

// graph may be int32 or int64 depending on jax x64 config.
// int32 layout: word[2*NSEG-1] = ends[NSEG-1] = N-1 (nonzero).
// int64 layout: word[2*NSEG-1] = high half of element NSEG-1 -> 0.
__device__ __forceinline__ void load_seg(const int* __restrict__ g, int s,
                                         int& st, int& en) {
    bool is64 = (g[2 * NSEG - 1] == 0);
    if (is64) {
        const long long* g64 = (const long long*)g;
        st = (int)g64[2 * s];
        en = (int)g64[2 * s + 1];
    } else {
        st = g[2 * s];
        en = g[2 * s + 1];
    }
}

// ---------------------------------------------------------------------------
// Kernel 1: blocks [0,TBLK) transpose W into g_WT (hidden under the memory
// phase). Blocks [TBLK,...): one block per segment, 128 threads. Warp w
// handles rows start+w+16i+{0,4,8,12}: 4 independent LDG.128 in flight.
// ---------------------------------------------------------------------------
__global__ void __launch_bounds__(128) sum_kernel(
    const float* __restrict__ input,
    const int*   __restrict__ graph,
    const float* __restrict__ W)
{
    if (blockIdx.x < TBLK) {
        int base = blockIdx.x * (D * D / TBLK);          // 1024 elems/block
#pragma unroll
        for (int i = 0; i < (D * D / TBLK) / 128; i++) { // 8 iters
            int lin = base + threadIdx.x + i * 128;
            int k = lin >> 7;
            int n = lin & 127;
            g_WT[lin] = W[n * D + k];
        }
        return;
    }

    const int s    = blockIdx.x - TBLK;
    const int c4   = threadIdx.x & 31;   // float4 column within row
    const int rl   = threadIdx.x >> 5;   // warp id 0..3

    int start, end;
    load_seg(graph, s, start, end);
    const int n = end - start + 1;

    const float4* base = (const float4*)input + (long long)start * 32 + c4;

    float4 acc = make_float4(0.f, 0.f, 0.f, 0.f);
    int r = rl;
    for (; r + 12 < n; r += 16) {
        const float4* p = base + (long long)r * 32;
        float4 v0 = p[0 * 32];
        float4 v1 = p[4 * 32];
        float4 v2 = p[8 * 32];
        float4 v3 = p[12 * 32];
        acc.x += (v0.x + v1.x) + (v2.x + v3.x);
        acc.y += (v0.y + v1.y) + (v2.y + v3.y);
        acc.z += (v0.z + v1.z) + (v2.z + v3.z);
        acc.w += (v0.w + v1.w) + (v2.w + v3.w);
    }
    for (; r < n; r += 4) {
        float4 v = base[(long long)r * 32];
        acc.x += v.x; acc.y += v.y; acc.z += v.z; acc.w += v.w;
    }

    __shared__ float4 red[4][32];
    red[rl][c4] = acc;
    __syncthreads();
    if (rl == 0) {
        float4 a = red[0][c4], b2 = red[1][c4], c = red[2][c4], d = red[3][c4];
        float4 t;
        t.x = (a.x + b2.x) + (c.x + d.x);
        t.y = (a.y + b2.y) + (c.y + d.y);
        t.z = (a.z + b2.z) + (c.z + d.z);
        t.w = (a.w + b2.w) + (c.w + d.w);
        ((float4*)g_sums)[s * 32 + c4] = t;
    }
}

// ---------------------------------------------------------------------------
// Kernel 2: out[m][n] = sum_k xs[m][k] * WT[k][n] + cnt_m * b[n]
// BM=72 segments/block, 288 threads -> 139 blocks = ONE wave on 148 SMs.
// Thread (ty,tx): 4 m x 8 n register tile. The 8 n's are split as
// {tx*4..tx*4+3} and {64+tx*4..64+tx*4+3}: within each 8-lane LDS.128
// phase the W reads cover 128 CONTIGUOUS bytes -> bank-conflict-free
// (the old tx*8 mapping was 2-way conflicted every k).
// ---------------------------------------------------------------------------
__global__ void __launch_bounds__(BLK_B) seg_gemm_kernel(
    const int*   __restrict__ graph,
    const float* __restrict__ b,
    float*       __restrict__ out)
{
    extern __shared__ float sm[];
    float* ws = sm;            // ws[k*D + n]  (64KB copy of g_WT)
    float* xs = sm + D * D;    // xs[m*XS_STRIDE + k]

    const int tid = threadIdx.x;
    const int m0  = blockIdx.x * BM;

    // Stage W^T: straight float4 copy, coalesced.
    {
        const float4* src = (const float4*)g_WT;
        for (int lin = tid; lin < D * D / 4; lin += BLK_B)
            ((float4*)ws)[lin] = src[lin];
    }
    // Stage x tile (72 rows x 32 float4 = 2304 = 8 * 288).
    {
#pragma unroll
        for (int i = 0; i < (BM * D / 4) / BLK_B; i++) {   // 8 iters
            int lin = tid + i * BLK_B;
            int m   = lin >> 5;
            int k4  = lin & 31;
            int seg = m0 + m;
            float4 v = make_float4(0.f, 0.f, 0.f, 0.f);
            if (seg < NSEG) v = ((const float4*)g_sums)[seg * 32 + k4];
            *(float4*)(xs + m * XS_STRIDE + k4 * 4) = v;
        }
    }
    __syncthreads();

    const int tx = tid & 15;    // n-groups: [tx*4, tx*4+4) and [64+tx*4, ...)
    const int ty = tid >> 4;    // m-group: m = ty*4 .. ty*4+3  (0..17)

    float acc[4][8];
#pragma unroll
    for (int i = 0; i < 4; i++)
#pragma unroll
        for (int j = 0; j < 8; j++) acc[i][j] = 0.f;

    const float* xp0 = xs + (ty * 4 + 0) * XS_STRIDE;
    const float* xp1 = xs + (ty * 4 + 1) * XS_STRIDE;
    const float* xp2 = xs + (ty * 4 + 2) * XS_STRIDE;
    const float* xp3 = xs + (ty * 4 + 3) * XS_STRIDE;
    const float* wp  = ws + tx * 4;          // first n-group
    // second n-group at +64 floats (+256B): also conflict-free per phase.

#pragma unroll 8
    for (int k = 0; k < D; k++) {
        float4 w0 = *(const float4*)(wp + k * D);
        float4 w1 = *(const float4*)(wp + k * D + 64);
        float x0 = xp0[k], x1 = xp1[k], x2 = xp2[k], x3 = xp3[k];

        acc[0][0] += x0 * w0.x; acc[0][1] += x0 * w0.y;
        acc[0][2] += x0 * w0.z; acc[0][3] += x0 * w0.w;
        acc[0][4] += x0 * w1.x; acc[0][5] += x0 * w1.y;
        acc[0][6] += x0 * w1.z; acc[0][7] += x0 * w1.w;

        acc[1][0] += x1 * w0.x; acc[1][1] += x1 * w0.y;
        acc[1][2] += x1 * w0.z; acc[1][3] += x1 * w0.w;
        acc[1][4] += x1 * w1.x; acc[1][5] += x1 * w1.y;
        acc[1][6] += x1 * w1.z; acc[1][7] += x1 * w1.w;

        acc[2][0] += x2 * w0.x; acc[2][1] += x2 * w0.y;
        acc[2][2] += x2 * w0.z; acc[2][3] += x2 * w0.w;
        acc[2][4] += x2 * w1.x; acc[2][5] += x2 * w1.y;
        acc[2][6] += x2 * w1.z; acc[2][7] += x2 * w1.w;

        acc[3][0] += x3 * w0.x; acc[3][1] += x3 * w0.y;
        acc[3][2] += x3 * w0.z; acc[3][3] += x3 * w0.w;
        acc[3][4] += x3 * w1.x; acc[3][5] += x3 * w1.y;
        acc[3][6] += x3 * w1.z; acc[3][7] += x3 * w1.w;
    }

    // Epilogue: + count * b. Two coalesced float4 groups at n=tx*4, 64+tx*4.
    float4 b0 = ((const float4*)b)[tx];
    float4 b1 = ((const float4*)b)[16 + tx];

#pragma unroll
    for (int i = 0; i < 4; i++) {
        int seg = m0 + ty * 4 + i;
        if (seg >= NSEG) continue;
        int st, en;
        load_seg(graph, seg, st, en);
        float cnt = (float)(en - st + 1);

        float4 o0, o1;
        o0.x = acc[i][0] + cnt * b0.x;
        o0.y = acc[i][1] + cnt * b0.y;
        o0.z = acc[i][2] + cnt * b0.z;
        o0.w = acc[i][3] + cnt * b0.w;
        o1.x = acc[i][4] + cnt * b1.x;
        o1.y = acc[i][5] + cnt * b1.y;
        o1.z = acc[i][6] + cnt * b1.z;
        o1.w = acc[i][7] + cnt * b1.w;

        float* op = out + (long long)seg * D;
        *(float4*)(op + tx * 4)      = o0;
        *(float4*)(op + 64 + tx * 4) = o1;
    }
}

extern "C" void kernel_launch(void* const* d_in, const int* in_sizes, int n_in,
                              void* d_out, int out_size) {
    const float* input = (const float*)d_in[0];
    const int*   graph = (const int*)  d_in[1];
    const float* W     = (const float*)d_in[2];
    const float* b     = (const float*)d_in[3];
    float*       out   = (float*)d_out;

    cudaFuncSetAttribute(seg_gemm_kernel,
                         cudaFuncAttributeMaxDynamicSharedMemorySize, SMEM_B);

    sum_kernel<<<TBLK + NSEG, 128>>>(input, graph, W);
    seg_gemm_kernel<<<(NSEG + BM - 1) / BM, BLK_B, SMEM_B>>>(graph, b, out);
}

// round 6
// speedup vs baseline: 1.6879x; 1.0040x over previous
#include <cuda_runtime.h>
#include <cstdint>

#define NSEG   10000
#define D      128
#define BM     72
#define BLK_B  288
#define TBLK   16
#define XS_STRIDE 132
#define SMEM_B ((D * D + BM * XS_STRIDE) * 4)   // 103552 bytes

__device__ float g_sums[NSEG * D];
__device__ float g_WT[D * D];     // g_WT[k*D + n] = W[n*D + k]

// graph may be int32 or int64 depending on jax x64 config.
// int32 layout: word[2*NSEG-1] = ends[NSEG-1] = N-1 (nonzero).
// int64 layout: word[2*NSEG-1] = high half of element NSEG-1 -> 0.
__device__ __forceinline__ void load_seg(const int* __restrict__ g, int s,
                                         int& st, int& en) {
    bool is64 = (g[2 * NSEG - 1] == 0);
    if (is64) {
        const long long* g64 = (const long long*)g;
        st = (int)g64[2 * s];
        en = (int)g64[2 * s + 1];
    } else {
        st = g[2 * s];
        en = g[2 * s + 1];
    }
}

// ---------------------------------------------------------------------------
// Kernel 1: blocks [0,TBLK) transpose W into g_WT (hidden under the memory
// phase). Blocks [TBLK,...): one block per segment, 128 threads. Warp w
// handles rows start+w+16i+{0,4,8,12}: 4 independent LDG.128 in flight.
// (UNCHANGED from R5 — protected.)
// ---------------------------------------------------------------------------
__global__ void __launch_bounds__(128) sum_kernel(
    const float* __restrict__ input,
    const int*   __restrict__ graph,
    const float* __restrict__ W)
{
    if (blockIdx.x < TBLK) {
        int base = blockIdx.x * (D * D / TBLK);          // 1024 elems/block
#pragma unroll
        for (int i = 0; i < (D * D / TBLK) / 128; i++) { // 8 iters
            int lin = base + threadIdx.x + i * 128;
            int k = lin >> 7;
            int n = lin & 127;
            g_WT[lin] = W[n * D + k];
        }
        return;
    }

    const int s    = blockIdx.x - TBLK;
    const int c4   = threadIdx.x & 31;   // float4 column within row
    const int rl   = threadIdx.x >> 5;   // warp id 0..3

    int start, end;
    load_seg(graph, s, start, end);
    const int n = end - start + 1;

    const float4* base = (const float4*)input + (long long)start * 32 + c4;

    float4 acc = make_float4(0.f, 0.f, 0.f, 0.f);
    int r = rl;
    for (; r + 12 < n; r += 16) {
        const float4* p = base + (long long)r * 32;
        float4 v0 = p[0 * 32];
        float4 v1 = p[4 * 32];
        float4 v2 = p[8 * 32];
        float4 v3 = p[12 * 32];
        acc.x += (v0.x + v1.x) + (v2.x + v3.x);
        acc.y += (v0.y + v1.y) + (v2.y + v3.y);
        acc.z += (v0.z + v1.z) + (v2.z + v3.z);
        acc.w += (v0.w + v1.w) + (v2.w + v3.w);
    }
    for (; r < n; r += 4) {
        float4 v = base[(long long)r * 32];
        acc.x += v.x; acc.y += v.y; acc.z += v.z; acc.w += v.w;
    }

    __shared__ float4 red[4][32];
    red[rl][c4] = acc;
    __syncthreads();
    if (rl == 0) {
        float4 a = red[0][c4], b2 = red[1][c4], c = red[2][c4], d = red[3][c4];
        float4 t;
        t.x = (a.x + b2.x) + (c.x + d.x);
        t.y = (a.y + b2.y) + (c.y + d.y);
        t.z = (a.z + b2.z) + (c.z + d.z);
        t.w = (a.w + b2.w) + (c.w + d.w);
        ((float4*)g_sums)[s * 32 + c4] = t;
    }
}

// ---------------------------------------------------------------------------
// Kernel 2: out[m][n] = sum_k xs[m][k] * WT[k][n] + cnt_m * b[n]
// BM=72/block, 288 threads -> 139 blocks = ONE wave. Thread = 4m x 8n.
// n's split {tx*4..+3} and {64+tx*4..+3} -> conflict-free W reads (R5).
// NEW: x loaded as float4 over k (1 LDS.128 per m per 4 k-steps):
// LDS drops 24 -> 12 per 128 FFMA and chains deepen.
// ---------------------------------------------------------------------------
__global__ void __launch_bounds__(BLK_B) seg_gemm_kernel(
    const int*   __restrict__ graph,
    const float* __restrict__ b,
    float*       __restrict__ out)
{
    extern __shared__ float sm[];
    float* ws = sm;            // ws[k*D + n]  (64KB copy of g_WT)
    float* xs = sm + D * D;    // xs[m*XS_STRIDE + k]

    const int tid = threadIdx.x;
    const int m0  = blockIdx.x * BM;

    // Stage W^T: straight float4 copy, coalesced.
    {
        const float4* src = (const float4*)g_WT;
        for (int lin = tid; lin < D * D / 4; lin += BLK_B)
            ((float4*)ws)[lin] = src[lin];
    }
    // Stage x tile (72 rows x 32 float4 = 2304 = 8 * 288).
    {
#pragma unroll
        for (int i = 0; i < (BM * D / 4) / BLK_B; i++) {   // 8 iters
            int lin = tid + i * BLK_B;
            int m   = lin >> 5;
            int k4  = lin & 31;
            int seg = m0 + m;
            float4 v = make_float4(0.f, 0.f, 0.f, 0.f);
            if (seg < NSEG) v = ((const float4*)g_sums)[seg * 32 + k4];
            *(float4*)(xs + m * XS_STRIDE + k4 * 4) = v;
        }
    }
    __syncthreads();

    const int tx = tid & 15;    // n-groups: [tx*4, +4) and [64+tx*4, +4)
    const int ty = tid >> 4;    // m-group: m = ty*4 .. ty*4+3  (0..17)

    float acc[4][8];
#pragma unroll
    for (int i = 0; i < 4; i++)
#pragma unroll
        for (int j = 0; j < 8; j++) acc[i][j] = 0.f;

    const float* xp0 = xs + (ty * 4 + 0) * XS_STRIDE;
    const float* xp1 = xs + (ty * 4 + 1) * XS_STRIDE;
    const float* xp2 = xs + (ty * 4 + 2) * XS_STRIDE;
    const float* xp3 = xs + (ty * 4 + 3) * XS_STRIDE;
    const float* wp  = ws + tx * 4;

#pragma unroll 2
    for (int k = 0; k < D; k += 4) {
        // One LDS.128 per m covers 4 k-steps.
        float4 xv0 = *(const float4*)(xp0 + k);
        float4 xv1 = *(const float4*)(xp1 + k);
        float4 xv2 = *(const float4*)(xp2 + k);
        float4 xv3 = *(const float4*)(xp3 + k);
        const float xr[4][4] = {
            {xv0.x, xv0.y, xv0.z, xv0.w},
            {xv1.x, xv1.y, xv1.z, xv1.w},
            {xv2.x, xv2.y, xv2.z, xv2.w},
            {xv3.x, xv3.y, xv3.z, xv3.w},
        };
#pragma unroll
        for (int kk = 0; kk < 4; kk++) {
            float4 w0 = *(const float4*)(wp + (k + kk) * D);
            float4 w1 = *(const float4*)(wp + (k + kk) * D + 64);
#pragma unroll
            for (int i = 0; i < 4; i++) {
                float x = xr[i][kk];
                acc[i][0] += x * w0.x; acc[i][1] += x * w0.y;
                acc[i][2] += x * w0.z; acc[i][3] += x * w0.w;
                acc[i][4] += x * w1.x; acc[i][5] += x * w1.y;
                acc[i][6] += x * w1.z; acc[i][7] += x * w1.w;
            }
        }
    }

    // Epilogue: + count * b. Two coalesced float4 groups at n=tx*4, 64+tx*4.
    float4 b0 = ((const float4*)b)[tx];
    float4 b1 = ((const float4*)b)[16 + tx];

#pragma unroll
    for (int i = 0; i < 4; i++) {
        int seg = m0 + ty * 4 + i;
        if (seg >= NSEG) continue;
        int st, en;
        load_seg(graph, seg, st, en);
        float cnt = (float)(en - st + 1);

        float4 o0, o1;
        o0.x = acc[i][0] + cnt * b0.x;
        o0.y = acc[i][1] + cnt * b0.y;
        o0.z = acc[i][2] + cnt * b0.z;
        o0.w = acc[i][3] + cnt * b0.w;
        o1.x = acc[i][4] + cnt * b1.x;
        o1.y = acc[i][5] + cnt * b1.y;
        o1.z = acc[i][6] + cnt * b1.z;
        o1.w = acc[i][7] + cnt * b1.w;

        float* op = out + (long long)seg * D;
        *(float4*)(op + tx * 4)      = o0;
        *(float4*)(op + 64 + tx * 4) = o1;
    }
}

extern "C" void kernel_launch(void* const* d_in, const int* in_sizes, int n_in,
                              void* d_out, int out_size) {
    const float* input = (const float*)d_in[0];
    const int*   graph = (const int*)  d_in[1];
    const float* W     = (const float*)d_in[2];
    const float* b     = (const float*)d_in[3];
    float*       out   = (float*)d_out;

    cudaFuncSetAttribute(seg_gemm_kernel,
                         cudaFuncAttributeMaxDynamicSharedMemorySize, SMEM_B);

    sum_kernel<<<TBLK + NSEG, 128>>>(input, graph, W);
    seg_gemm_kernel<<<(NSEG + BM - 1) / BM, BLK_B, SMEM_B>>>(graph, b, out);
}

// round 7
// speedup vs baseline: 1.7232x; 1.0209x over previous
#include <cuda_runtime.h>
#include <cstdint>

#define NSEG   10000
#define D      128
#define BM     72
#define BLK_B  576
#define TBLK   16
#define XS_STRIDE 132
#define SMEM_B ((D * D + BM * XS_STRIDE) * 4)   // 103552 bytes

__device__ float g_sums[NSEG * D];
__device__ float g_WT[D * D];     // g_WT[k*D + n] = W[n*D + k]

// graph may be int32 or int64 depending on jax x64 config.
// int32 layout: word[2*NSEG-1] = ends[NSEG-1] = N-1 (nonzero).
// int64 layout: word[2*NSEG-1] = high half of element NSEG-1 -> 0.
__device__ __forceinline__ void load_seg(const int* __restrict__ g, int s,
                                         int& st, int& en) {
    bool is64 = (g[2 * NSEG - 1] == 0);
    if (is64) {
        const long long* g64 = (const long long*)g;
        st = (int)g64[2 * s];
        en = (int)g64[2 * s + 1];
    } else {
        st = g[2 * s];
        en = g[2 * s + 1];
    }
}

// ---------------------------------------------------------------------------
// Kernel 1: blocks [0,TBLK) transpose W into g_WT (hidden under the memory
// phase). Blocks [TBLK,...): one block per segment, 128 threads. Warp w
// handles rows start+w+16i+{0,4,8,12}: 4 independent LDG.128 in flight.
// (UNCHANGED — protected.)
// ---------------------------------------------------------------------------
__global__ void __launch_bounds__(128) sum_kernel(
    const float* __restrict__ input,
    const int*   __restrict__ graph,
    const float* __restrict__ W)
{
    if (blockIdx.x < TBLK) {
        int base = blockIdx.x * (D * D / TBLK);          // 1024 elems/block
#pragma unroll
        for (int i = 0; i < (D * D / TBLK) / 128; i++) { // 8 iters
            int lin = base + threadIdx.x + i * 128;
            int k = lin >> 7;
            int n = lin & 127;
            g_WT[lin] = W[n * D + k];
        }
        return;
    }

    const int s    = blockIdx.x - TBLK;
    const int c4   = threadIdx.x & 31;   // float4 column within row
    const int rl   = threadIdx.x >> 5;   // warp id 0..3

    int start, end;
    load_seg(graph, s, start, end);
    const int n = end - start + 1;

    const float4* base = (const float4*)input + (long long)start * 32 + c4;

    float4 acc = make_float4(0.f, 0.f, 0.f, 0.f);
    int r = rl;
    for (; r + 12 < n; r += 16) {
        const float4* p = base + (long long)r * 32;
        float4 v0 = p[0 * 32];
        float4 v1 = p[4 * 32];
        float4 v2 = p[8 * 32];
        float4 v3 = p[12 * 32];
        acc.x += (v0.x + v1.x) + (v2.x + v3.x);
        acc.y += (v0.y + v1.y) + (v2.y + v3.y);
        acc.z += (v0.z + v1.z) + (v2.z + v3.z);
        acc.w += (v0.w + v1.w) + (v2.w + v3.w);
    }
    for (; r < n; r += 4) {
        float4 v = base[(long long)r * 32];
        acc.x += v.x; acc.y += v.y; acc.z += v.z; acc.w += v.w;
    }

    __shared__ float4 red[4][32];
    red[rl][c4] = acc;
    __syncthreads();
    if (rl == 0) {
        float4 a = red[0][c4], b2 = red[1][c4], c = red[2][c4], d = red[3][c4];
        float4 t;
        t.x = (a.x + b2.x) + (c.x + d.x);
        t.y = (a.y + b2.y) + (c.y + d.y);
        t.z = (a.z + b2.z) + (c.z + d.z);
        t.w = (a.w + b2.w) + (c.w + d.w);
        ((float4*)g_sums)[s * 32 + c4] = t;
    }
}

// ---------------------------------------------------------------------------
// Kernel 2: out[m][n] = sum_k xs[m][k] * WT[k][n] + cnt_m * b[n]
// BM=72/block, 576 threads -> 139 blocks = ONE wave, 18 warps/SM
// (4.5/SMSP, double R6) for latency hiding. Thread = 2m x 8n.
// n's split {tx*4..+3} and {64+tx*4..+3} -> conflict-free W reads.
// ---------------------------------------------------------------------------
__global__ void __launch_bounds__(BLK_B) seg_gemm_kernel(
    const int*   __restrict__ graph,
    const float* __restrict__ b,
    float*       __restrict__ out)
{
    extern __shared__ float sm[];
    float* ws = sm;            // ws[k*D + n]  (64KB copy of g_WT)
    float* xs = sm + D * D;    // xs[m*XS_STRIDE + k]

    const int tid = threadIdx.x;
    const int m0  = blockIdx.x * BM;

    // Stage W^T: straight float4 copy, coalesced.
    {
        const float4* src = (const float4*)g_WT;
        for (int lin = tid; lin < D * D / 4; lin += BLK_B)
            ((float4*)ws)[lin] = src[lin];
    }
    // Stage x tile (72 rows x 32 float4 = 2304 = 4 * 576).
    {
#pragma unroll
        for (int i = 0; i < (BM * D / 4) / BLK_B; i++) {   // 4 iters
            int lin = tid + i * BLK_B;
            int m   = lin >> 5;
            int k4  = lin & 31;
            int seg = m0 + m;
            float4 v = make_float4(0.f, 0.f, 0.f, 0.f);
            if (seg < NSEG) v = ((const float4*)g_sums)[seg * 32 + k4];
            *(float4*)(xs + m * XS_STRIDE + k4 * 4) = v;
        }
    }
    __syncthreads();

    const int tx = tid & 15;    // n-groups: [tx*4, +4) and [64+tx*4, +4)
    const int ty = tid >> 4;    // m-group: m = ty*2, ty*2+1  (ty 0..35)

    float acc[2][8];
#pragma unroll
    for (int i = 0; i < 2; i++)
#pragma unroll
        for (int j = 0; j < 8; j++) acc[i][j] = 0.f;

    const float* xp0 = xs + (ty * 2 + 0) * XS_STRIDE;
    const float* xp1 = xs + (ty * 2 + 1) * XS_STRIDE;
    const float* wp  = ws + tx * 4;

#pragma unroll 2
    for (int k = 0; k < D; k += 4) {
        float4 xv0 = *(const float4*)(xp0 + k);
        float4 xv1 = *(const float4*)(xp1 + k);
        const float xr[2][4] = {
            {xv0.x, xv0.y, xv0.z, xv0.w},
            {xv1.x, xv1.y, xv1.z, xv1.w},
        };
#pragma unroll
        for (int kk = 0; kk < 4; kk++) {
            float4 w0 = *(const float4*)(wp + (k + kk) * D);
            float4 w1 = *(const float4*)(wp + (k + kk) * D + 64);
#pragma unroll
            for (int i = 0; i < 2; i++) {
                float x = xr[i][kk];
                acc[i][0] += x * w0.x; acc[i][1] += x * w0.y;
                acc[i][2] += x * w0.z; acc[i][3] += x * w0.w;
                acc[i][4] += x * w1.x; acc[i][5] += x * w1.y;
                acc[i][6] += x * w1.z; acc[i][7] += x * w1.w;
            }
        }
    }

    // Epilogue: + count * b. Two coalesced float4 groups at n=tx*4, 64+tx*4.
    float4 b0 = ((const float4*)b)[tx];
    float4 b1 = ((const float4*)b)[16 + tx];

#pragma unroll
    for (int i = 0; i < 2; i++) {
        int seg = m0 + ty * 2 + i;
        if (seg >= NSEG) continue;
        int st, en;
        load_seg(graph, seg, st, en);
        float cnt = (float)(en - st + 1);

        float4 o0, o1;
        o0.x = acc[i][0] + cnt * b0.x;
        o0.y = acc[i][1] + cnt * b0.y;
        o0.z = acc[i][2] + cnt * b0.z;
        o0.w = acc[i][3] + cnt * b0.w;
        o1.x = acc[i][4] + cnt * b1.x;
        o1.y = acc[i][5] + cnt * b1.y;
        o1.z = acc[i][6] + cnt * b1.z;
        o1.w = acc[i][7] + cnt * b1.w;

        float* op = out + (long long)seg * D;
        *(float4*)(op + tx * 4)      = o0;
        *(float4*)(op + 64 + tx * 4) = o1;
    }
}

extern "C" void kernel_launch(void* const* d_in, const int* in_sizes, int n_in,
                              void* d_out, int out_size) {
    const float* input = (const float*)d_in[0];
    const int*   graph = (const int*)  d_in[1];
    const float* W     = (const float*)d_in[2];
    const float* b     = (const float*)d_in[3];
    float*       out   = (float*)d_out;

    cudaFuncSetAttribute(seg_gemm_kernel,
                         cudaFuncAttributeMaxDynamicSharedMemorySize, SMEM_B);

    sum_kernel<<<TBLK + NSEG, 128>>>(input, graph, W);
    seg_gemm_kernel<<<(NSEG + BM - 1) / BM, BLK_B, SMEM_B>>>(graph, b, out);
}